// round 4
// baseline (speedup 1.0000x reference)
#include <cuda_runtime.h>
#include <math.h>
#include <stdint.h>

#define B_ 8
#define C_ 512
#define T_ 8192
#define P_ 512
#define K_ 30
#define M_ (B_ * P_)          // 4096 rows through the MLP

// output layout (concatenated tuple, fp32)
#define VIDEO_OFF 0
#define JOINT_OFF (VIDEO_OFF + B_ * K_)                 // 240
#define CLS_OFF   (JOINT_OFF + M_ * K_)                 // 123120
#define DET_OFF   (CLS_OFF + M_ * K_)                   // 246000
#define H7_OFF    (DET_OFF + M_ * K_)                   // 368880

// ------------------------- scratch (no cudaMalloc) -------------------------
__device__ float g_pooled[B_ * C_ * P_];   // 8 MB  [B*C, P]
__device__ float g_feats[M_ * C_];         // 8 MB  [4096, 512]
__device__ float g_h6[M_ * 1024];          // 16 MB [4096, 1024]
__device__ float g_whd[64 * 512];          // packed head weights
__device__ float g_bhd[64];
__device__ float g_ghd[M_ * 64];           // head logits (cls|det|pad)
__device__ float g_cprob[M_ * K_];
__device__ float g_dmax[B_ * K_], g_dsum[B_ * K_];

// ------------------------- f32x2 helpers -------------------------
__device__ __forceinline__ void ffma2(unsigned long long& d,
                                      unsigned long long a, unsigned long long b) {
    asm("fma.rn.f32x2 %0, %1, %2, %0;" : "+l"(d) : "l"(a), "l"(b));
}
__device__ __forceinline__ void unpack2(unsigned long long d, float& lo, float& hi) {
    asm("mov.b64 {%0, %1}, %2;" : "=f"(lo), "=f"(hi) : "l"(d));
}

__device__ __forceinline__ float warp_sum(float v) {
#pragma unroll
    for (int o = 16; o > 0; o >>= 1) v += __shfl_xor_sync(0xffffffffu, v, o);
    return v;
}
__device__ __forceinline__ float warp_max(float v) {
#pragma unroll
    for (int o = 16; o > 0; o >>= 1) v = fmaxf(v, __shfl_xor_sync(0xffffffffu, v, o));
    return v;
}

// ---------------------------------------------------------------------------
// Kernel 1: per-(b,c) row scan in smem + answer all proposals (coalesced out)
// ---------------------------------------------------------------------------
__global__ void pool_kernel(const float* __restrict__ x,
                            const void* __restrict__ boxes_raw,
                            float* __restrict__ pooled) {
    const int bc = blockIdx.x;
    const int b = bc / C_;
    const float* row = x + (size_t)bc * T_;

    __shared__ float cs[256 * 33];
    __shared__ float part[256];
    const int t = threadIdx.x;

    for (int j4 = t; j4 < T_ / 4; j4 += 256) {
        float4 v = reinterpret_cast<const float4*>(row)[j4];
        int j = j4 * 4;
        int base = (j >> 5) * 33 + (j & 31);
        cs[base + 0] = v.x; cs[base + 1] = v.y; cs[base + 2] = v.z; cs[base + 3] = v.w;
    }
    __syncthreads();

    float run = 0.f;
    const int base = t * 33;
#pragma unroll
    for (int i = 0; i < 32; i++) { run += cs[base + i]; cs[base + i] = run; }
    part[t] = run;
    __syncthreads();
    for (int off = 1; off < 256; off <<= 1) {
        float v = part[t];
        float add = (t >= off) ? part[t - off] : 0.f;
        __syncthreads();
        part[t] = v + add;
        __syncthreads();
    }
    const float ofs = (t > 0) ? part[t - 1] : 0.f;
#pragma unroll
    for (int i = 0; i < 32; i++) cs[base + i] += ofs;
    __syncthreads();

    const long long* b64all = (const long long*)boxes_raw;
    long long s0 = b64all[0], e0 = b64all[1];
    bool is64 = (s0 >= 0 && s0 < T_ && e0 >= 1 && e0 <= T_ && e0 > s0);

    for (int p = t; p < P_; p += 256) {
        int s, e;
        if (is64) {
            const long long* bb = b64all + (size_t)b * P_ * 2;
            s = (int)bb[2 * p]; e = (int)bb[2 * p + 1];
        } else {
            const int* bb = ((const int*)boxes_raw) + (size_t)b * P_ * 2;
            s = bb[2 * p]; e = bb[2 * p + 1];
        }
        int ei = e - 1;
        float ge = cs[(ei >> 5) * 33 + (ei & 31)];
        float gs = 0.f;
        if (s > 0) { int si = s - 1; gs = cs[(si >> 5) * 33 + (si & 31)]; }
        pooled[(size_t)bc * P_ + p] = (ge - gs) / (float)(e - s);
    }
}

// ---------------------------------------------------------------------------
// Kernel 2: transpose [B,C,P] -> [B*P, C]
// ---------------------------------------------------------------------------
__global__ void transpose_k(const float* __restrict__ pooled,
                            float* __restrict__ feats) {
    __shared__ float t[32][33];
    const int b = blockIdx.z, c0 = blockIdx.x * 32, p0 = blockIdx.y * 32;
    const int tx = threadIdx.x, ty = threadIdx.y;
#pragma unroll
    for (int i = 0; i < 32; i += 8)
        t[ty + i][tx] = pooled[((size_t)(b * C_ + c0 + ty + i)) * P_ + p0 + tx];
    __syncthreads();
#pragma unroll
    for (int i = 0; i < 32; i += 8)
        feats[((size_t)(b * P_ + p0 + ty + i)) * C_ + c0 + tx] = t[tx][ty + i];
}

// Kernel 3: pack Wc,Wd -> 64x512 padded head weight + bias
__global__ void prep_whd(const float* __restrict__ Wc, const float* __restrict__ bc,
                         const float* __restrict__ Wd, const float* __restrict__ bd,
                         float* __restrict__ wo, float* __restrict__ bo) {
    int i = blockIdx.x * blockDim.x + threadIdx.x;
    if (i < 64 * 512) {
        int r = i >> 9, k = i & 511;
        wo[i] = (r < 30) ? Wc[r * 512 + k] : ((r < 60) ? Wd[(r - 30) * 512 + k] : 0.f);
    }
    if (i < 64) bo[i] = (i < 30) ? bc[i] : ((i < 60) ? bd[i - 30] : 0.f);
}

// ---------------------------------------------------------------------------
// f32x2 diag/anti-diag NT SGEMM: C[M,N] = act(A[M,K] @ W[N,K]^T + bias)
// BM=128, BK=16. Warp = 4(ty) x 8(tx). Block = 8 warps (4x2).
// Thread microtile: 8 rows (4 m-pairs) x 2*NJ cols (NJ n-pairs, strided by 16).
// B smem pre-interleaved per n-pair: {b0,b1,b1,b0} -> one LDS.128 gives
// natural+swapped pair; zero packing MOVs in inner loop.
// ---------------------------------------------------------------------------
#define AS_STRIDE 132
#define AS_PER_STAGE (16 * AS_STRIDE)      // 2112 floats

template <int BN, bool RELU>
__global__ __launch_bounds__(256, 2) void gemm2x(
    const float* __restrict__ A, const float* __restrict__ W,
    const float* __restrict__ bias, float* __restrict__ Cmat,
    int K, int ldC) {
    constexpr int NJ  = BN / 32;     // n-pairs per thread
    constexpr int NPT = BN / 2;      // n-pairs per block
    constexpr int BI_PER_STAGE = 16 * NPT * 4;   // floats

    extern __shared__ float sm[];
    float* Asm = sm;                          // 2 stages, AS_PER_STAGE each
    float* Bim = sm + 2 * AS_PER_STAGE;       // 2 stages, BI_PER_STAGE each

    const int tid = threadIdx.x;
    const int wid = tid >> 5, lane = tid & 31;
    const int ly = lane >> 3, lx = lane & 7;
    const int ty = (wid & 3) * 4 + ly;        // 0..15
    const int tx = (wid >> 2) * 8 + lx;       // 0..15
    const int m0 = blockIdx.y * 128, n0 = blockIdx.x * BN;

    const float* Ag = A + (size_t)m0 * K;
    const float* Wg = W + (size_t)n0 * K;

    unsigned long long accd[4][NJ], accx[4][NJ];
#pragma unroll
    for (int i = 0; i < 4; i++)
#pragma unroll
        for (int j = 0; j < NJ; j++) { accd[i][j] = 0ull; accx[i][j] = 0ull; }

    // staging indices
    const int ar = tid >> 2, aq = tid & 3;           // A: 2 float4 per thread
    const bool bact = tid < NPT * 4;
    const int bnp = tid >> 2, bq = tid & 3;          // B: 1 cell-group per thread

    float4 pa0, pa1, va, vb;

    // ---- prologue: load + store stage 0
    {
        pa0 = *(const float4*)(Ag + (size_t)ar * K + aq * 4);
        pa1 = *(const float4*)(Ag + (size_t)(ar + 64) * K + aq * 4);
        if (bact) {
            va = *(const float4*)(Wg + (size_t)(2 * bnp) * K + bq * 4);
            vb = *(const float4*)(Wg + (size_t)(2 * bnp + 1) * K + bq * 4);
        }
        float* as0 = Asm;
        as0[(aq * 4 + 0) * AS_STRIDE + ar] = pa0.x;
        as0[(aq * 4 + 1) * AS_STRIDE + ar] = pa0.y;
        as0[(aq * 4 + 2) * AS_STRIDE + ar] = pa0.z;
        as0[(aq * 4 + 3) * AS_STRIDE + ar] = pa0.w;
        as0[(aq * 4 + 0) * AS_STRIDE + ar + 64] = pa1.x;
        as0[(aq * 4 + 1) * AS_STRIDE + ar + 64] = pa1.y;
        as0[(aq * 4 + 2) * AS_STRIDE + ar + 64] = pa1.z;
        as0[(aq * 4 + 3) * AS_STRIDE + ar + 64] = pa1.w;
        if (bact) {
            float* bs0 = Bim;
            *(float4*)(bs0 + ((bq * 4 + 0) * NPT + bnp) * 4) = make_float4(va.x, vb.x, vb.x, va.x);
            *(float4*)(bs0 + ((bq * 4 + 1) * NPT + bnp) * 4) = make_float4(va.y, vb.y, vb.y, va.y);
            *(float4*)(bs0 + ((bq * 4 + 2) * NPT + bnp) * 4) = make_float4(va.z, vb.z, vb.z, va.z);
            *(float4*)(bs0 + ((bq * 4 + 3) * NPT + bnp) * 4) = make_float4(va.w, vb.w, vb.w, va.w);
        }
    }
    __syncthreads();

    const int NIT = K >> 4;
    for (int it = 0; it < NIT; it++) {
        const int s = it & 1;
        const bool more = (it + 1 < NIT);
        if (more) {
            const int k0 = (it + 1) << 4;
            pa0 = *(const float4*)(Ag + (size_t)ar * K + k0 + aq * 4);
            pa1 = *(const float4*)(Ag + (size_t)(ar + 64) * K + k0 + aq * 4);
            if (bact) {
                va = *(const float4*)(Wg + (size_t)(2 * bnp) * K + k0 + bq * 4);
                vb = *(const float4*)(Wg + (size_t)(2 * bnp + 1) * K + k0 + bq * 4);
            }
        }

        const float* Ask = Asm + s * AS_PER_STAGE;
        const float* Bik = Bim + s * BI_PER_STAGE;
#pragma unroll
        for (int kk = 0; kk < 16; kk++) {
            ulonglong2 A0 = *(const ulonglong2*)(Ask + kk * AS_STRIDE + ty * 8);
            ulonglong2 A1 = *(const ulonglong2*)(Ask + kk * AS_STRIDE + ty * 8 + 4);
            unsigned long long a[4] = {A0.x, A0.y, A1.x, A1.y};
#pragma unroll
            for (int j = 0; j < NJ; j++) {
                ulonglong2 Bv = *(const ulonglong2*)(Bik + (kk * NPT + tx + j * 16) * 4);
#pragma unroll
                for (int i = 0; i < 4; i++) {
                    ffma2(accd[i][j], a[i], Bv.x);
                    ffma2(accx[i][j], a[i], Bv.y);
                }
            }
        }

        if (more) {
            const int sn = s ^ 1;
            float* asd = Asm + sn * AS_PER_STAGE;
            asd[(aq * 4 + 0) * AS_STRIDE + ar] = pa0.x;
            asd[(aq * 4 + 1) * AS_STRIDE + ar] = pa0.y;
            asd[(aq * 4 + 2) * AS_STRIDE + ar] = pa0.z;
            asd[(aq * 4 + 3) * AS_STRIDE + ar] = pa0.w;
            asd[(aq * 4 + 0) * AS_STRIDE + ar + 64] = pa1.x;
            asd[(aq * 4 + 1) * AS_STRIDE + ar + 64] = pa1.y;
            asd[(aq * 4 + 2) * AS_STRIDE + ar + 64] = pa1.z;
            asd[(aq * 4 + 3) * AS_STRIDE + ar + 64] = pa1.w;
            if (bact) {
                float* bsd = Bim + sn * BI_PER_STAGE;
                *(float4*)(bsd + ((bq * 4 + 0) * NPT + bnp) * 4) = make_float4(va.x, vb.x, vb.x, va.x);
                *(float4*)(bsd + ((bq * 4 + 1) * NPT + bnp) * 4) = make_float4(va.y, vb.y, vb.y, va.y);
                *(float4*)(bsd + ((bq * 4 + 2) * NPT + bnp) * 4) = make_float4(va.z, vb.z, vb.z, va.z);
                *(float4*)(bsd + ((bq * 4 + 3) * NPT + bnp) * 4) = make_float4(va.w, vb.w, vb.w, va.w);
            }
            __syncthreads();
        }
    }

    // ---- epilogue: unscramble diag/anti-diag, add bias, act, store
#pragma unroll
    for (int j = 0; j < NJ; j++) {
        const int np = tx + j * 16;
        const float b0 = bias[n0 + 2 * np];
        const float b1 = bias[n0 + 2 * np + 1];
#pragma unroll
        for (int i = 0; i < 4; i++) {
            float de, dh, xe, xh;
            unpack2(accd[i][j], de, dh);
            unpack2(accx[i][j], xe, xh);
            float r0c0 = de + b0, r0c1 = xe + b1;
            float r1c0 = xh + b0, r1c1 = dh + b1;
            if (RELU) {
                r0c0 = fmaxf(r0c0, 0.f); r0c1 = fmaxf(r0c1, 0.f);
                r1c0 = fmaxf(r1c0, 0.f); r1c1 = fmaxf(r1c1, 0.f);
            }
            const size_t r0 = (size_t)(m0 + ty * 8 + 2 * i);
            const size_t c0 = (size_t)(n0 + 2 * np);
            *(float2*)(Cmat + r0 * ldC + c0) = make_float2(r0c0, r0c1);
            *(float2*)(Cmat + (r0 + 1) * ldC + c0) = make_float2(r1c0, r1c1);
        }
    }
}

// ---------------------------------------------------------------------------
// heads postprocess: per-row class softmax + split cls/det
// ---------------------------------------------------------------------------
__global__ __launch_bounds__(256) void headpost_kernel(
    const float* __restrict__ ghd, float* __restrict__ clsO,
    float* __restrict__ detO, float* __restrict__ cprob) {
    const int row = blockIdx.x * 8 + (threadIdx.x >> 5);
    const int lane = threadIdx.x & 31;
    const bool act = lane < K_;
    float c = act ? ghd[(size_t)row * 64 + lane] : -INFINITY;
    float d = act ? ghd[(size_t)row * 64 + K_ + lane] : 0.f;
    float mx = warp_max(c);
    float e = act ? expf(c - mx) : 0.f;
    float s = warp_sum(e);
    if (act) {
        clsO[(size_t)row * K_ + lane] = c;
        detO[(size_t)row * K_ + lane] = d;
        cprob[(size_t)row * K_ + lane] = e / s;
    }
}

// det softmax stats per (b,k)
__global__ void detstats_kernel(const float* __restrict__ detL) {
    const int gw = blockIdx.x * 8 + (threadIdx.x >> 5);
    if (gw >= B_ * K_) return;
    const int lane = threadIdx.x & 31;
    const int b = gw / K_, k = gw % K_;
    float vals[16];
    float mx = -INFINITY;
#pragma unroll
    for (int i = 0; i < 16; i++) {
        int p = lane + 32 * i;
        vals[i] = detL[((size_t)(b * P_ + p)) * K_ + k];
        mx = fmaxf(mx, vals[i]);
    }
    mx = warp_max(mx);
    float s = 0.f;
#pragma unroll
    for (int i = 0; i < 16; i++) s += expf(vals[i] - mx);
    s = warp_sum(s);
    if (lane == 0) { g_dmax[gw] = mx; g_dsum[gw] = s; }
}

__global__ __launch_bounds__(256) void joint_kernel(
    const float* __restrict__ detL, const float* __restrict__ cprob,
    float* __restrict__ joint, float* __restrict__ video) {
    const int bk = blockIdx.x;
    const int b = bk / K_, k = bk % K_;
    const float mx = g_dmax[bk];
    const float inv = 1.f / g_dsum[bk];
    __shared__ float red[256];
    float local = 0.f;
    for (int p = threadIdx.x; p < P_; p += 256) {
        size_t idx = ((size_t)(b * P_ + p)) * K_ + k;
        float dp = expf(detL[idx] - mx) * inv;
        float j = cprob[idx] * dp;
        joint[idx] = j;
        local += j;
    }
    red[threadIdx.x] = local;
    __syncthreads();
    for (int s = 128; s > 0; s >>= 1) {
        if (threadIdx.x < s) red[threadIdx.x] += red[threadIdx.x + s];
        __syncthreads();
    }
    if (threadIdx.x == 0) video[bk] = red[0];
}

// ---------------------------------------------------------------------------
extern "C" void kernel_launch(void* const* d_in, const int* in_sizes, int n_in,
                              void* d_out, int out_size) {
    const float* x  = (const float*)d_in[0];
    const void*  bx = d_in[1];
    const float* W6 = (const float*)d_in[2];
    const float* b6 = (const float*)d_in[3];
    const float* W7 = (const float*)d_in[4];
    const float* b7 = (const float*)d_in[5];
    const float* Wc = (const float*)d_in[6];
    const float* bc = (const float*)d_in[7];
    const float* Wd = (const float*)d_in[8];
    const float* bd = (const float*)d_in[9];
    float* out = (float*)d_out;

    float *pooled, *feats, *h6, *whd, *bhd, *ghd, *cprob;
    cudaGetSymbolAddress((void**)&pooled, g_pooled);
    cudaGetSymbolAddress((void**)&feats, g_feats);
    cudaGetSymbolAddress((void**)&h6, g_h6);
    cudaGetSymbolAddress((void**)&whd, g_whd);
    cudaGetSymbolAddress((void**)&bhd, g_bhd);
    cudaGetSymbolAddress((void**)&ghd, g_ghd);
    cudaGetSymbolAddress((void**)&cprob, g_cprob);

    float* h7    = out + H7_OFF;
    float* clsO  = out + CLS_OFF;
    float* detO  = out + DET_OFF;
    float* joint = out + JOINT_OFF;
    float* video = out + VIDEO_OFF;

    // dynamic smem sizes (bytes)
    const int SM128 = (2 * AS_PER_STAGE + 2 * 16 * 64 * 4) * 4;   // 49664
    const int SM64  = (2 * AS_PER_STAGE + 2 * 16 * 32 * 4) * 4;   // 33280
    cudaFuncSetAttribute(gemm2x<128, true>, cudaFuncAttributeMaxDynamicSharedMemorySize, SM128);
    cudaFuncSetAttribute(gemm2x<64, false>, cudaFuncAttributeMaxDynamicSharedMemorySize, SM64);

    // 1. pooled [B*C, P]
    pool_kernel<<<B_ * C_, 256>>>(x, bx, pooled);
    // 2. feats [M, C]
    transpose_k<<<dim3(C_ / 32, P_ / 32, B_), dim3(32, 8)>>>(pooled, feats);
    // 3. packed head weights
    prep_whd<<<(64 * 512 + 255) / 256, 256>>>(Wc, bc, Wd, bd, whd, bhd);

    // 4. h6 = relu(feats @ W6^T + b6) : M=4096, N=1024, K=512
    gemm2x<128, true><<<dim3(8, 32), 256, SM128>>>(feats, W6, b6, h6, 512, 1024);
    // 5. h7 = relu(h6 @ W7^T + b7) : M=4096, N=512, K=1024 -> out
    gemm2x<128, true><<<dim3(4, 32), 256, SM128>>>(h6, W7, b7, h7, 1024, 512);
    // 6. heads: ghd = h7 @ Whd^T + bhd : M=4096, N=64, K=512
    gemm2x<64, false><<<dim3(1, 32), 256, SM64>>>(h7, whd, bhd, ghd, 512, 64);

    // 7. class softmax + split
    headpost_kernel<<<M_ / 8, 256>>>(ghd, clsO, detO, cprob);
    // 8. det softmax stats
    detstats_kernel<<<(B_ * K_ + 7) / 8, 256>>>(detO);
    // 9. joint & video
    joint_kernel<<<B_ * K_, 256>>>(detO, cprob, joint, video);
}

// round 5
// speedup vs baseline: 1.7803x; 1.7803x over previous
#include <cuda_runtime.h>
#include <cuda_bf16.h>
#include <math.h>
#include <stdint.h>

#define B_ 8
#define C_ 512
#define T_ 8192
#define P_ 512
#define K_ 30
#define M_ (B_ * P_)          // 4096 rows through the MLP

// output layout (concatenated tuple, fp32)
#define VIDEO_OFF 0
#define JOINT_OFF (VIDEO_OFF + B_ * K_)                 // 240
#define CLS_OFF   (JOINT_OFF + M_ * K_)                 // 123120
#define DET_OFF   (CLS_OFF + M_ * K_)                   // 246000
#define H7_OFF    (DET_OFF + M_ * K_)                   // 368880

// ------------------------- scratch (no cudaMalloc) -------------------------
__device__ float          g_pooled[B_ * C_ * P_];        // [B*C, P]
__device__ __nv_bfloat16  g_fH[M_ * C_],   g_fL[M_ * C_];
__device__ __nv_bfloat16  g_W6H[1024 * 512], g_W6L[1024 * 512];
__device__ __nv_bfloat16  g_W7H[512 * 1024], g_W7L[512 * 1024];
__device__ __nv_bfloat16  g_h6H[M_ * 1024],  g_h6L[M_ * 1024];
__device__ __nv_bfloat16  g_h7H[M_ * 512],   g_h7L[M_ * 512];
__device__ __nv_bfloat16  g_WhdH[128 * 512], g_WhdL[128 * 512];
__device__ float          g_bhd[128];
__device__ float          g_ghd[M_ * 128];               // head logits, ld=128
__device__ float          g_cprob[M_ * K_];
__device__ float          g_dmax[B_ * K_], g_dsum[B_ * K_];

// ------------------------- helpers -------------------------
__device__ __forceinline__ uint32_t smem_u32(const void* p) {
    uint32_t a;
    asm("{ .reg .u64 t; cvta.to.shared.u64 t, %1; cvt.u32.u64 %0, t; }" : "=r"(a) : "l"(p));
    return a;
}
__device__ __forceinline__ void ldsm4(uint32_t addr, uint32_t r[4]) {
    asm volatile("ldmatrix.sync.aligned.m8n8.x4.shared.b16 {%0,%1,%2,%3}, [%4];"
        : "=r"(r[0]), "=r"(r[1]), "=r"(r[2]), "=r"(r[3]) : "r"(addr));
}
__device__ __forceinline__ void mma16816(float c[4], const uint32_t a[4],
                                         uint32_t b0, uint32_t b1) {
    asm volatile("mma.sync.aligned.m16n8k16.row.col.f32.bf16.bf16.f32 "
        "{%0,%1,%2,%3}, {%4,%5,%6,%7}, {%8,%9}, {%0,%1,%2,%3};"
        : "+f"(c[0]), "+f"(c[1]), "+f"(c[2]), "+f"(c[3])
        : "r"(a[0]), "r"(a[1]), "r"(a[2]), "r"(a[3]), "r"(b0), "r"(b1));
}
#define CPASYNC(dst, src) \
    asm volatile("cp.async.cg.shared.global [%0], [%1], 16;" :: "r"(dst), "l"(src))
#define CP_COMMIT() asm volatile("cp.async.commit_group;" ::: "memory")
#define CP_WAIT(n)  asm volatile("cp.async.wait_group %0;" :: "n"(n) : "memory")

__device__ __forceinline__ float warp_sum(float v) {
#pragma unroll
    for (int o = 16; o > 0; o >>= 1) v += __shfl_xor_sync(0xffffffffu, v, o);
    return v;
}
__device__ __forceinline__ float warp_max(float v) {
#pragma unroll
    for (int o = 16; o > 0; o >>= 1) v = fmaxf(v, __shfl_xor_sync(0xffffffffu, v, o));
    return v;
}

// ---------------------------------------------------------------------------
// Kernel 1: per-(b,c) row scan in smem + answer all proposals (coalesced out)
// ---------------------------------------------------------------------------
__global__ void pool_kernel(const float* __restrict__ x,
                            const void* __restrict__ boxes_raw,
                            float* __restrict__ pooled) {
    const int bc = blockIdx.x;
    const int b = bc / C_;
    const float* row = x + (size_t)bc * T_;

    __shared__ float cs[256 * 33];
    __shared__ float part[256];
    const int t = threadIdx.x;

    for (int j4 = t; j4 < T_ / 4; j4 += 256) {
        float4 v = reinterpret_cast<const float4*>(row)[j4];
        int j = j4 * 4;
        int base = (j >> 5) * 33 + (j & 31);
        cs[base + 0] = v.x; cs[base + 1] = v.y; cs[base + 2] = v.z; cs[base + 3] = v.w;
    }
    __syncthreads();

    float run = 0.f;
    const int base = t * 33;
#pragma unroll
    for (int i = 0; i < 32; i++) { run += cs[base + i]; cs[base + i] = run; }
    part[t] = run;
    __syncthreads();
    for (int off = 1; off < 256; off <<= 1) {
        float v = part[t];
        float add = (t >= off) ? part[t - off] : 0.f;
        __syncthreads();
        part[t] = v + add;
        __syncthreads();
    }
    const float ofs = (t > 0) ? part[t - 1] : 0.f;
#pragma unroll
    for (int i = 0; i < 32; i++) cs[base + i] += ofs;
    __syncthreads();

    const long long* b64all = (const long long*)boxes_raw;
    long long s0 = b64all[0], e0 = b64all[1];
    bool is64 = (s0 >= 0 && s0 < T_ && e0 >= 1 && e0 <= T_ && e0 > s0);

    for (int p = t; p < P_; p += 256) {
        int s, e;
        if (is64) {
            const long long* bb = b64all + (size_t)b * P_ * 2;
            s = (int)bb[2 * p]; e = (int)bb[2 * p + 1];
        } else {
            const int* bb = ((const int*)boxes_raw) + (size_t)b * P_ * 2;
            s = bb[2 * p]; e = bb[2 * p + 1];
        }
        int ei = e - 1;
        float ge = cs[(ei >> 5) * 33 + (ei & 31)];
        float gs = 0.f;
        if (s > 0) { int si = s - 1; gs = cs[(si >> 5) * 33 + (si & 31)]; }
        pooled[(size_t)bc * P_ + p] = (ge - gs) / (float)(e - s);
    }
}

// ---------------------------------------------------------------------------
// Kernel 2: transpose [B,C,P] -> [B*P, C] with bf16 hi/lo split
// ---------------------------------------------------------------------------
__global__ void transpose_split(const float* __restrict__ pooled,
                                __nv_bfloat16* __restrict__ fH,
                                __nv_bfloat16* __restrict__ fL) {
    __shared__ float t[32][33];
    const int b = blockIdx.z, c0 = blockIdx.x * 32, p0 = blockIdx.y * 32;
    const int tx = threadIdx.x, ty = threadIdx.y;
#pragma unroll
    for (int i = 0; i < 32; i += 8)
        t[ty + i][tx] = pooled[((size_t)(b * C_ + c0 + ty + i)) * P_ + p0 + tx];
    __syncthreads();
#pragma unroll
    for (int i = 0; i < 32; i += 8) {
        size_t row = (size_t)(b * P_ + p0 + ty + i);
        float v = t[tx][ty + i];
        __nv_bfloat16 h = __float2bfloat16_rn(v);
        fH[row * C_ + c0 + tx] = h;
        fL[row * C_ + c0 + tx] = __float2bfloat16_rn(v - __bfloat162float(h));
    }
}

// Kernel 3: fp32 -> bf16 hi/lo split (weights)
__global__ void split_bf16(const float* __restrict__ in,
                           __nv_bfloat16* __restrict__ oh,
                           __nv_bfloat16* __restrict__ ol, int n) {
    for (int i = blockIdx.x * blockDim.x + threadIdx.x; i < n; i += gridDim.x * blockDim.x) {
        float v = in[i];
        __nv_bfloat16 h = __float2bfloat16_rn(v);
        oh[i] = h;
        ol[i] = __float2bfloat16_rn(v - __bfloat162float(h));
    }
}

// Kernel 4: pack Wc,Wd -> 128x512 padded head weight (hi/lo) + bias
__global__ void prep_whd(const float* __restrict__ Wc, const float* __restrict__ bc,
                         const float* __restrict__ Wd, const float* __restrict__ bd,
                         __nv_bfloat16* __restrict__ oh, __nv_bfloat16* __restrict__ ol,
                         float* __restrict__ bo) {
    int i = blockIdx.x * blockDim.x + threadIdx.x;
    if (i < 128 * 512) {
        int r = i >> 9, k = i & 511;
        float v = (r < 30) ? Wc[r * 512 + k] : ((r < 60) ? Wd[(r - 30) * 512 + k] : 0.f);
        __nv_bfloat16 h = __float2bfloat16_rn(v);
        oh[i] = h;
        ol[i] = __float2bfloat16_rn(v - __bfloat162float(h));
    }
    if (i < 128) bo[i] = (i < 30) ? bc[i] : ((i < 60) ? bd[i - 30] : 0.f);
}

// ---------------------------------------------------------------------------
// mma.sync bf16-split GEMM: C[128x128 tile] = act(A[M,K] @ W[N,K]^T + bias)
// 256 threads = 8 warps (2m x 4n), warp tile 64x32, atoms m16n8k16.
// 3-term split: AH*BH + AH*BL + AL*BH.  cp.async 2-stage, ldmatrix frags.
// MODE 0: relu -> bf16 hi/lo.  MODE 1: relu -> f32 + bf16 hi/lo.  MODE 2: f32.
// ---------------------------------------------------------------------------
#define STG_BYTES 32768      // per stage: A 16KB (2 splits) + B 16KB

template <int MODE>
__global__ __launch_bounds__(256) void gemm_mma(
    const __nv_bfloat16* __restrict__ AH, const __nv_bfloat16* __restrict__ AL,
    const __nv_bfloat16* __restrict__ BH, const __nv_bfloat16* __restrict__ BL,
    const float* __restrict__ bias, int K, int ldC,
    float* __restrict__ outF, __nv_bfloat16* __restrict__ outH,
    __nv_bfloat16* __restrict__ outL) {

    extern __shared__ char smem[];
    const uint32_t sbase = smem_u32(smem);

    const int tid = threadIdx.x;
    const int lane = tid & 31, wid = tid >> 5;
    const int wm = wid >> 2, wn = wid & 3;
    const int m0 = blockIdx.y * 128, n0 = blockIdx.x * 128;

    // ---- global->smem staging indices (4 A-uint4 + 4 B-uint4 per thread)
    uint32_t offA[4], offB[4];
    const __nv_bfloat16* srcA[4];
    const __nv_bfloat16* srcB[4];
#pragma unroll
    for (int u = 0; u < 4; u++) {
        int id = tid + u * 256;
        int split = id >> 9, g = id & 511, row = g >> 2, seg = g & 3;
        uint32_t sw = (uint32_t)(((((row & 1) << 2) + seg) ^ ((row >> 1) & 7)) << 4);
        uint32_t off = (uint32_t)(split * 8192 + ((row >> 1) * 128)) + sw;
        offA[u] = off;
        offB[u] = off + 16384;
        srcA[u] = (split ? AL : AH) + (size_t)(m0 + row) * K + seg * 8;
        srcB[u] = (split ? BL : BH) + (size_t)(n0 + row) * K + seg * 8;
    }

    // ---- ldmatrix per-lane address components
    const int laneRow = (lane & 7) | (((lane >> 3) & 1) << 3);
    const int segAdd = (lane >> 4) & 1;
    uint32_t pA1[4]; int pA2[4], pA3[4];
#pragma unroll
    for (int ma = 0; ma < 4; ma++) {
        int row = wm * 64 + ma * 16 + laneRow;
        pA1[ma] = (uint32_t)((row >> 1) * 128);
        pA2[ma] = (row & 1) << 2;
        pA3[ma] = (row >> 1) & 7;
    }
    uint32_t pB1[2]; int pB2[2], pB3[2];
#pragma unroll
    for (int nb = 0; nb < 2; nb++) {
        int row = wn * 32 + nb * 16 + laneRow;
        pB1[nb] = (uint32_t)((row >> 1) * 128);
        pB2[nb] = (row & 1) << 2;
        pB3[nb] = (row >> 1) & 7;
    }

    float acc[4][4][4];
#pragma unroll
    for (int i = 0; i < 4; i++)
#pragma unroll
        for (int j = 0; j < 4; j++)
#pragma unroll
            for (int q = 0; q < 4; q++) acc[i][j][q] = 0.f;

    const int NIT = K >> 5;

    // prologue: stage 0
#pragma unroll
    for (int u = 0; u < 4; u++) {
        CPASYNC(sbase + offA[u], srcA[u]);
        CPASYNC(sbase + offB[u], srcB[u]);
    }
    CP_COMMIT();

    for (int it = 0; it < NIT; it++) {
        const int st = it & 1;
        if (it + 1 < NIT) {
            const int kpos = (it + 1) << 5;
            const uint32_t sb = sbase + (st ^ 1) * STG_BYTES;
#pragma unroll
            for (int u = 0; u < 4; u++) {
                CPASYNC(sb + offA[u], srcA[u] + kpos);
                CPASYNC(sb + offB[u], srcB[u] + kpos);
            }
            CP_COMMIT();
            CP_WAIT(1);
        } else {
            CP_WAIT(0);
        }
        __syncthreads();

        const uint32_t stb = sbase + st * STG_BYTES;
#pragma unroll
        for (int ks = 0; ks < 2; ks++) {
            uint32_t aH[4][4], aL[4][4];
#pragma unroll
            for (int ma = 0; ma < 4; ma++) {
                uint32_t swz = (uint32_t)(((pA2[ma] + ks * 2 + segAdd) ^ pA3[ma]) << 4);
                ldsm4(stb + pA1[ma] + swz, aH[ma]);
                ldsm4(stb + 8192 + pA1[ma] + swz, aL[ma]);
            }
            uint32_t bH[2][4], bL[2][4];
#pragma unroll
            for (int nb = 0; nb < 2; nb++) {
                uint32_t swz = (uint32_t)(((pB2[nb] + ks * 2 + segAdd) ^ pB3[nb]) << 4);
                ldsm4(stb + 16384 + pB1[nb] + swz, bH[nb]);
                ldsm4(stb + 16384 + 8192 + pB1[nb] + swz, bL[nb]);
            }
#pragma unroll
            for (int ma = 0; ma < 4; ma++)
#pragma unroll
                for (int na = 0; na < 4; na++) {
                    uint32_t b0h = bH[na >> 1][na & 1], b1h = bH[na >> 1][2 + (na & 1)];
                    uint32_t b0l = bL[na >> 1][na & 1], b1l = bL[na >> 1][2 + (na & 1)];
                    mma16816(acc[ma][na], aH[ma], b0h, b1h);
                    mma16816(acc[ma][na], aH[ma], b0l, b1l);
                    mma16816(acc[ma][na], aL[ma], b0h, b1h);
                }
        }
        __syncthreads();
    }

    // ---- epilogue
    const int tr = lane >> 2, tc = (lane & 3) * 2;
#pragma unroll
    for (int ma = 0; ma < 4; ma++) {
        const int r0 = m0 + wm * 64 + ma * 16 + tr;
#pragma unroll
        for (int na = 0; na < 4; na++) {
            const int col = n0 + wn * 32 + na * 8 + tc;
            const float b0 = bias[col], b1 = bias[col + 1];
            float v00 = acc[ma][na][0] + b0, v01 = acc[ma][na][1] + b1;
            float v10 = acc[ma][na][2] + b0, v11 = acc[ma][na][3] + b1;
            if (MODE != 2) {
                v00 = fmaxf(v00, 0.f); v01 = fmaxf(v01, 0.f);
                v10 = fmaxf(v10, 0.f); v11 = fmaxf(v11, 0.f);
            }
            if (MODE == 1 || MODE == 2) {
                *(float2*)(outF + (size_t)r0 * ldC + col) = make_float2(v00, v01);
                *(float2*)(outF + (size_t)(r0 + 8) * ldC + col) = make_float2(v10, v11);
            }
            if (MODE == 0 || MODE == 1) {
                __nv_bfloat162 h0, h1, l0, l1;
                h0.x = __float2bfloat16_rn(v00); h0.y = __float2bfloat16_rn(v01);
                h1.x = __float2bfloat16_rn(v10); h1.y = __float2bfloat16_rn(v11);
                l0.x = __float2bfloat16_rn(v00 - __bfloat162float(h0.x));
                l0.y = __float2bfloat16_rn(v01 - __bfloat162float(h0.y));
                l1.x = __float2bfloat16_rn(v10 - __bfloat162float(h1.x));
                l1.y = __float2bfloat16_rn(v11 - __bfloat162float(h1.y));
                *(__nv_bfloat162*)(outH + (size_t)r0 * ldC + col) = h0;
                *(__nv_bfloat162*)(outH + (size_t)(r0 + 8) * ldC + col) = h1;
                *(__nv_bfloat162*)(outL + (size_t)r0 * ldC + col) = l0;
                *(__nv_bfloat162*)(outL + (size_t)(r0 + 8) * ldC + col) = l1;
            }
        }
    }
}

// ---------------------------------------------------------------------------
// heads postprocess: per-row class softmax + split cls/det (ghd ld = 128)
// ---------------------------------------------------------------------------
__global__ __launch_bounds__(256) void headpost_kernel(
    const float* __restrict__ ghd, float* __restrict__ clsO,
    float* __restrict__ detO, float* __restrict__ cprob) {
    const int row = blockIdx.x * 8 + (threadIdx.x >> 5);
    const int lane = threadIdx.x & 31;
    const bool act = lane < K_;
    float c = act ? ghd[(size_t)row * 128 + lane] : -INFINITY;
    float d = act ? ghd[(size_t)row * 128 + K_ + lane] : 0.f;
    float mx = warp_max(c);
    float e = act ? expf(c - mx) : 0.f;
    float s = warp_sum(e);
    if (act) {
        clsO[(size_t)row * K_ + lane] = c;
        detO[(size_t)row * K_ + lane] = d;
        cprob[(size_t)row * K_ + lane] = e / s;
    }
}

// det softmax stats per (b,k)
__global__ void detstats_kernel(const float* __restrict__ detL) {
    const int gw = blockIdx.x * 8 + (threadIdx.x >> 5);
    if (gw >= B_ * K_) return;
    const int lane = threadIdx.x & 31;
    const int b = gw / K_, k = gw % K_;
    float vals[16];
    float mx = -INFINITY;
#pragma unroll
    for (int i = 0; i < 16; i++) {
        int p = lane + 32 * i;
        vals[i] = detL[((size_t)(b * P_ + p)) * K_ + k];
        mx = fmaxf(mx, vals[i]);
    }
    mx = warp_max(mx);
    float s = 0.f;
#pragma unroll
    for (int i = 0; i < 16; i++) s += expf(vals[i] - mx);
    s = warp_sum(s);
    if (lane == 0) { g_dmax[gw] = mx; g_dsum[gw] = s; }
}

__global__ __launch_bounds__(256) void joint_kernel(
    const float* __restrict__ detL, const float* __restrict__ cprob,
    float* __restrict__ joint, float* __restrict__ video) {
    const int bk = blockIdx.x;
    const int b = bk / K_, k = bk % K_;
    const float mx = g_dmax[bk];
    const float inv = 1.f / g_dsum[bk];
    __shared__ float red[256];
    float local = 0.f;
    for (int p = threadIdx.x; p < P_; p += 256) {
        size_t idx = ((size_t)(b * P_ + p)) * K_ + k;
        float dp = expf(detL[idx] - mx) * inv;
        float j = cprob[idx] * dp;
        joint[idx] = j;
        local += j;
    }
    red[threadIdx.x] = local;
    __syncthreads();
    for (int s = 128; s > 0; s >>= 1) {
        if (threadIdx.x < s) red[threadIdx.x] += red[threadIdx.x + s];
        __syncthreads();
    }
    if (threadIdx.x == 0) video[bk] = red[0];
}

// ---------------------------------------------------------------------------
extern "C" void kernel_launch(void* const* d_in, const int* in_sizes, int n_in,
                              void* d_out, int out_size) {
    const float* x  = (const float*)d_in[0];
    const void*  bx = d_in[1];
    const float* W6 = (const float*)d_in[2];
    const float* b6 = (const float*)d_in[3];
    const float* W7 = (const float*)d_in[4];
    const float* b7 = (const float*)d_in[5];
    const float* Wc = (const float*)d_in[6];
    const float* bc = (const float*)d_in[7];
    const float* Wd = (const float*)d_in[8];
    const float* bd = (const float*)d_in[9];
    float* out = (float*)d_out;

    float *pooled, *bhd, *ghd, *cprob;
    __nv_bfloat16 *fH, *fL, *W6H, *W6L, *W7H, *W7L, *h6H, *h6L, *h7H, *h7L, *WhdH, *WhdL;
    cudaGetSymbolAddress((void**)&pooled, g_pooled);
    cudaGetSymbolAddress((void**)&fH, g_fH);   cudaGetSymbolAddress((void**)&fL, g_fL);
    cudaGetSymbolAddress((void**)&W6H, g_W6H); cudaGetSymbolAddress((void**)&W6L, g_W6L);
    cudaGetSymbolAddress((void**)&W7H, g_W7H); cudaGetSymbolAddress((void**)&W7L, g_W7L);
    cudaGetSymbolAddress((void**)&h6H, g_h6H); cudaGetSymbolAddress((void**)&h6L, g_h6L);
    cudaGetSymbolAddress((void**)&h7H, g_h7H); cudaGetSymbolAddress((void**)&h7L, g_h7L);
    cudaGetSymbolAddress((void**)&WhdH, g_WhdH); cudaGetSymbolAddress((void**)&WhdL, g_WhdL);
    cudaGetSymbolAddress((void**)&bhd, g_bhd);
    cudaGetSymbolAddress((void**)&ghd, g_ghd);
    cudaGetSymbolAddress((void**)&cprob, g_cprob);

    float* h7    = out + H7_OFF;
    float* clsO  = out + CLS_OFF;
    float* detO  = out + DET_OFF;
    float* joint = out + JOINT_OFF;
    float* video = out + VIDEO_OFF;

    const int SMEM = 2 * STG_BYTES;   // 64 KB
    cudaFuncSetAttribute(gemm_mma<0>, cudaFuncAttributeMaxDynamicSharedMemorySize, SMEM);
    cudaFuncSetAttribute(gemm_mma<1>, cudaFuncAttributeMaxDynamicSharedMemorySize, SMEM);
    cudaFuncSetAttribute(gemm_mma<2>, cudaFuncAttributeMaxDynamicSharedMemorySize, SMEM);

    // 1. pooled [B*C, P]
    pool_kernel<<<B_ * C_, 256>>>(x, bx, pooled);
    // 2. feats bf16 hi/lo [M, C]
    transpose_split<<<dim3(C_ / 32, P_ / 32, B_), dim3(32, 8)>>>(pooled, fH, fL);
    // 3. weight splits
    split_bf16<<<512, 256>>>(W6, W6H, W6L, 1024 * 512);
    split_bf16<<<512, 256>>>(W7, W7H, W7L, 512 * 1024);
    prep_whd<<<(128 * 512 + 255) / 256, 256>>>(Wc, bc, Wd, bd, WhdH, WhdL, bhd);

    // 4. h6 = relu(feats @ W6^T + b6) : M=4096, N=1024, K=512
    gemm_mma<0><<<dim3(8, 32), 256, SMEM>>>(fH, fL, W6H, W6L, b6, 512, 1024,
                                            nullptr, h6H, h6L);
    // 5. h7 = relu(h6 @ W7^T + b7) : M=4096, N=512, K=1024 (f32 -> out + bf16 pair)
    gemm_mma<1><<<dim3(4, 32), 256, SMEM>>>(h6H, h6L, W7H, W7L, b7, 1024, 512,
                                            h7, h7H, h7L);
    // 6. heads: ghd = h7 @ Whd^T + bhd : M=4096, N=128(pad), K=512
    gemm_mma<2><<<dim3(1, 32), 256, SMEM>>>(h7H, h7L, WhdH, WhdL, bhd, 512, 128,
                                            ghd, nullptr, nullptr);

    // 7. class softmax + split
    headpost_kernel<<<M_ / 8, 256>>>(ghd, clsO, detO, cprob);
    // 8. det softmax stats
    detstats_kernel<<<(B_ * K_ + 7) / 8, 256>>>(detO);
    // 9. joint & video
    joint_kernel<<<B_ * K_, 256>>>(detO, cprob, joint, video);
}

// round 6
// speedup vs baseline: 1.8688x; 1.0497x over previous
#include <cuda_runtime.h>
#include <cuda_bf16.h>
#include <math.h>
#include <stdint.h>

#define B_ 8
#define C_ 512
#define T_ 8192
#define P_ 512
#define K_ 30
#define M_ (B_ * P_)          // 4096 rows through the MLP

// output layout (concatenated tuple, fp32)
#define VIDEO_OFF 0
#define JOINT_OFF (VIDEO_OFF + B_ * K_)                 // 240
#define CLS_OFF   (JOINT_OFF + M_ * K_)                 // 123120
#define DET_OFF   (CLS_OFF + M_ * K_)                   // 246000
#define H7_OFF    (DET_OFF + M_ * K_)                   // 368880

// ------------------------- scratch (no cudaMalloc) -------------------------
__device__ float          g_pooled[B_ * C_ * P_];        // [B*C, P]
__device__ __nv_bfloat16  g_fH[M_ * C_],   g_fL[M_ * C_];
__device__ __nv_bfloat16  g_W6H[1024 * 512], g_W6L[1024 * 512];
__device__ __nv_bfloat16  g_W7H[512 * 1024], g_W7L[512 * 1024];
__device__ __nv_bfloat16  g_h6H[M_ * 1024],  g_h6L[M_ * 1024];
__device__ __nv_bfloat16  g_h7H[M_ * 512],   g_h7L[M_ * 512];
__device__ __nv_bfloat16  g_WhdH[128 * 512], g_WhdL[128 * 512];
__device__ float          g_bhd[128];
__device__ float          g_ghd[M_ * 64];                // head logits, ld=64
__device__ float          g_cprob[M_ * K_];

// ------------------------- helpers -------------------------
__device__ __forceinline__ uint32_t smem_u32(const void* p) {
    uint32_t a;
    asm("{ .reg .u64 t; cvta.to.shared.u64 t, %1; cvt.u32.u64 %0, t; }" : "=r"(a) : "l"(p));
    return a;
}
__device__ __forceinline__ void ldsm4(uint32_t addr, uint32_t r[4]) {
    asm volatile("ldmatrix.sync.aligned.m8n8.x4.shared.b16 {%0,%1,%2,%3}, [%4];"
        : "=r"(r[0]), "=r"(r[1]), "=r"(r[2]), "=r"(r[3]) : "r"(addr));
}
__device__ __forceinline__ void mma16816(float c[4], const uint32_t a[4],
                                         uint32_t b0, uint32_t b1) {
    asm volatile("mma.sync.aligned.m16n8k16.row.col.f32.bf16.bf16.f32 "
        "{%0,%1,%2,%3}, {%4,%5,%6,%7}, {%8,%9}, {%0,%1,%2,%3};"
        : "+f"(c[0]), "+f"(c[1]), "+f"(c[2]), "+f"(c[3])
        : "r"(a[0]), "r"(a[1]), "r"(a[2]), "r"(a[3]), "r"(b0), "r"(b1));
}
#define CPASYNC(dst, src) \
    asm volatile("cp.async.cg.shared.global [%0], [%1], 16;" :: "r"(dst), "l"(src))
#define CP_COMMIT() asm volatile("cp.async.commit_group;" ::: "memory")
#define CP_WAIT(n)  asm volatile("cp.async.wait_group %0;" :: "n"(n) : "memory")

__device__ __forceinline__ float warp_sum(float v) {
#pragma unroll
    for (int o = 16; o > 0; o >>= 1) v += __shfl_xor_sync(0xffffffffu, v, o);
    return v;
}
__device__ __forceinline__ float warp_max(float v) {
#pragma unroll
    for (int o = 16; o > 0; o >>= 1) v = fmaxf(v, __shfl_xor_sync(0xffffffffu, v, o));
    return v;
}

// ---------------------------------------------------------------------------
// Kernel 1: per-(b,c) row scan in smem (shuffle-based) + answer proposals
// ---------------------------------------------------------------------------
__global__ void pool_kernel(const float* __restrict__ x,
                            const void* __restrict__ boxes_raw,
                            float* __restrict__ pooled) {
    const int bc = blockIdx.x;
    const int b = bc / C_;
    const float* row = x + (size_t)bc * T_;

    __shared__ float cs[256 * 33];
    __shared__ float wsum[8];
    const int t = threadIdx.x;
    const int warp = t >> 5, lane = t & 31;

    for (int j4 = t; j4 < T_ / 4; j4 += 256) {
        float4 v = reinterpret_cast<const float4*>(row)[j4];
        int j = j4 * 4;
        int base = (j >> 5) * 33 + (j & 31);
        cs[base + 0] = v.x; cs[base + 1] = v.y; cs[base + 2] = v.z; cs[base + 3] = v.w;
    }
    __syncthreads();

    // local sequential scan over this thread's 32 elements
    float run = 0.f;
    const int base = t * 33;
#pragma unroll
    for (int i = 0; i < 32; i++) { run += cs[base + i]; cs[base + i] = run; }

    // warp-level inclusive scan of per-thread totals (shfl)
    float incl = run;
#pragma unroll
    for (int o = 1; o < 32; o <<= 1) {
        float up = __shfl_up_sync(0xffffffffu, incl, o);
        if (lane >= o) incl += up;
    }
    if (lane == 31) wsum[warp] = incl;
    __syncthreads();

    float wofs = 0.f;
#pragma unroll
    for (int wv = 0; wv < 8; wv++) wofs += (wv < warp) ? wsum[wv] : 0.f;
    const float ofs = wofs + (incl - run);   // exclusive prefix for this thread
#pragma unroll
    for (int i = 0; i < 32; i++) cs[base + i] += ofs;
    __syncthreads();

    const long long* b64all = (const long long*)boxes_raw;
    long long s0 = b64all[0], e0 = b64all[1];
    bool is64 = (s0 >= 0 && s0 < T_ && e0 >= 1 && e0 <= T_ && e0 > s0);

    for (int p = t; p < P_; p += 256) {
        int s, e;
        if (is64) {
            const long long* bb = b64all + (size_t)b * P_ * 2;
            s = (int)bb[2 * p]; e = (int)bb[2 * p + 1];
        } else {
            const int* bb = ((const int*)boxes_raw) + (size_t)b * P_ * 2;
            s = bb[2 * p]; e = bb[2 * p + 1];
        }
        int ei = e - 1;
        float ge = cs[(ei >> 5) * 33 + (ei & 31)];
        float gs = 0.f;
        if (s > 0) { int si = s - 1; gs = cs[(si >> 5) * 33 + (si & 31)]; }
        pooled[(size_t)bc * P_ + p] = (ge - gs) / (float)(e - s);
    }
}

// ---------------------------------------------------------------------------
// Kernel 2: transpose [B,C,P] -> [B*P, C] with bf16 hi/lo split
// ---------------------------------------------------------------------------
__global__ void transpose_split(const float* __restrict__ pooled,
                                __nv_bfloat16* __restrict__ fH,
                                __nv_bfloat16* __restrict__ fL) {
    __shared__ float t[32][33];
    const int b = blockIdx.z, c0 = blockIdx.x * 32, p0 = blockIdx.y * 32;
    const int tx = threadIdx.x, ty = threadIdx.y;
#pragma unroll
    for (int i = 0; i < 32; i += 8)
        t[ty + i][tx] = pooled[((size_t)(b * C_ + c0 + ty + i)) * P_ + p0 + tx];
    __syncthreads();
#pragma unroll
    for (int i = 0; i < 32; i += 8) {
        size_t row = (size_t)(b * P_ + p0 + ty + i);
        float v = t[tx][ty + i];
        __nv_bfloat16 h = __float2bfloat16_rn(v);
        fH[row * C_ + c0 + tx] = h;
        fL[row * C_ + c0 + tx] = __float2bfloat16_rn(v - __bfloat162float(h));
    }
}

// ---------------------------------------------------------------------------
// Kernel 3: all weight prep fused (W6, W7, packed Whd + bias)
// ---------------------------------------------------------------------------
#define N_W6 (1024 * 512)
#define N_W7 (512 * 1024)
#define N_WHD (128 * 512)
__global__ void prep_all(const float* __restrict__ W6,
                         const float* __restrict__ W7,
                         const float* __restrict__ Wc, const float* __restrict__ bc,
                         const float* __restrict__ Wd, const float* __restrict__ bd,
                         __nv_bfloat16* __restrict__ W6H, __nv_bfloat16* __restrict__ W6L,
                         __nv_bfloat16* __restrict__ W7H, __nv_bfloat16* __restrict__ W7L,
                         __nv_bfloat16* __restrict__ WhdH, __nv_bfloat16* __restrict__ WhdL,
                         float* __restrict__ bhd) {
    const int NT = N_W6 + N_W7 + N_WHD;
    for (int i = blockIdx.x * blockDim.x + threadIdx.x; i < NT; i += gridDim.x * blockDim.x) {
        float v;
        __nv_bfloat16* oh;
        __nv_bfloat16* ol;
        int li;
        if (i < N_W6) { li = i; v = W6[li]; oh = W6H; ol = W6L; }
        else if (i < N_W6 + N_W7) { li = i - N_W6; v = W7[li]; oh = W7H; ol = W7L; }
        else {
            li = i - N_W6 - N_W7;
            int r = li >> 9, k = li & 511;
            v = (r < 30) ? Wc[r * 512 + k] : ((r < 60) ? Wd[(r - 30) * 512 + k] : 0.f);
            oh = WhdH; ol = WhdL;
            if (li < 128) bhd[li] = (li < 30) ? bc[li] : ((li < 60) ? bd[li - 30] : 0.f);
        }
        __nv_bfloat16 h = __float2bfloat16_rn(v);
        oh[li] = h;
        ol[li] = __float2bfloat16_rn(v - __bfloat162float(h));
    }
}

// ---------------------------------------------------------------------------
// mma.sync bf16-split GEMM: C[128x128 tile] = act(A[M,K] @ W[N,K]^T + bias)
// 256 threads = 8 warps (2m x 4n), warp tile 64x32, atoms m16n8k16.
// 3-term split: AH*BH + AH*BL + AL*BH.  cp.async 3-stage, ldmatrix frags.
// MODE 0: relu -> bf16 hi/lo.  MODE 1: relu -> f32 + bf16 hi/lo.
// MODE 2: f32, only cols < 64, ldC applies.
// ---------------------------------------------------------------------------
#define STG_BYTES 32768      // per stage: A 16KB (2 splits) + B 16KB
#define N_STAGES 3

template <int MODE>
__global__ __launch_bounds__(256) void gemm_mma(
    const __nv_bfloat16* __restrict__ AH, const __nv_bfloat16* __restrict__ AL,
    const __nv_bfloat16* __restrict__ BH, const __nv_bfloat16* __restrict__ BL,
    const float* __restrict__ bias, int K, int ldC,
    float* __restrict__ outF, __nv_bfloat16* __restrict__ outH,
    __nv_bfloat16* __restrict__ outL) {

    extern __shared__ char smem[];
    const uint32_t sbase = smem_u32(smem);

    const int tid = threadIdx.x;
    const int lane = tid & 31, wid = tid >> 5;
    const int wm = wid >> 2, wn = wid & 3;
    const int m0 = blockIdx.y * 128, n0 = blockIdx.x * 128;

    // ---- global->smem staging indices (4 A-uint4 + 4 B-uint4 per thread)
    uint32_t offA[4], offB[4];
    const __nv_bfloat16* srcA[4];
    const __nv_bfloat16* srcB[4];
#pragma unroll
    for (int u = 0; u < 4; u++) {
        int id = tid + u * 256;
        int split = id >> 9, g = id & 511, row = g >> 2, seg = g & 3;
        uint32_t sw = (uint32_t)(((((row & 1) << 2) + seg) ^ ((row >> 1) & 7)) << 4);
        uint32_t off = (uint32_t)(split * 8192 + ((row >> 1) * 128)) + sw;
        offA[u] = off;
        offB[u] = off + 16384;
        srcA[u] = (split ? AL : AH) + (size_t)(m0 + row) * K + seg * 8;
        srcB[u] = (split ? BL : BH) + (size_t)(n0 + row) * K + seg * 8;
    }

    // ---- ldmatrix per-lane address components
    const int laneRow = (lane & 7) | (((lane >> 3) & 1) << 3);
    const int segAdd = (lane >> 4) & 1;
    uint32_t pA1[4]; int pA2[4], pA3[4];
#pragma unroll
    for (int ma = 0; ma < 4; ma++) {
        int row = wm * 64 + ma * 16 + laneRow;
        pA1[ma] = (uint32_t)((row >> 1) * 128);
        pA2[ma] = (row & 1) << 2;
        pA3[ma] = (row >> 1) & 7;
    }
    uint32_t pB1[2]; int pB2[2], pB3[2];
#pragma unroll
    for (int nb = 0; nb < 2; nb++) {
        int row = wn * 32 + nb * 16 + laneRow;
        pB1[nb] = (uint32_t)((row >> 1) * 128);
        pB2[nb] = (row & 1) << 2;
        pB3[nb] = (row >> 1) & 7;
    }

    float acc[4][4][4];
#pragma unroll
    for (int i = 0; i < 4; i++)
#pragma unroll
        for (int j = 0; j < 4; j++)
#pragma unroll
            for (int q = 0; q < 4; q++) acc[i][j][q] = 0.f;

    const int NIT = K >> 5;

    // prologue: stages 0 and 1
#pragma unroll
    for (int u = 0; u < 4; u++) {
        CPASYNC(sbase + offA[u], srcA[u]);
        CPASYNC(sbase + offB[u], srcB[u]);
    }
    CP_COMMIT();
    if (NIT > 1) {
        const uint32_t sb = sbase + STG_BYTES;
#pragma unroll
        for (int u = 0; u < 4; u++) {
            CPASYNC(sb + offA[u], srcA[u] + 32);
            CPASYNC(sb + offB[u], srcB[u] + 32);
        }
        CP_COMMIT();
    }

    int st = 0, ld = 2 % N_STAGES;
    for (int it = 0; it < NIT; it++) {
        if (it + 1 < NIT) { CP_WAIT(1); } else { CP_WAIT(0); }
        __syncthreads();

        // issue loads for stage it+2 (buffer freed by barrier above)
        if (it + 2 < NIT) {
            const int kpos = (it + 2) << 5;
            const uint32_t sb = sbase + ld * STG_BYTES;
#pragma unroll
            for (int u = 0; u < 4; u++) {
                CPASYNC(sb + offA[u], srcA[u] + kpos);
                CPASYNC(sb + offB[u], srcB[u] + kpos);
            }
            CP_COMMIT();
        }

        const uint32_t stb = sbase + st * STG_BYTES;
#pragma unroll
        for (int ks = 0; ks < 2; ks++) {
            uint32_t aH[4][4], aL[4][4];
#pragma unroll
            for (int ma = 0; ma < 4; ma++) {
                uint32_t swz = (uint32_t)(((pA2[ma] + ks * 2 + segAdd) ^ pA3[ma]) << 4);
                ldsm4(stb + pA1[ma] + swz, aH[ma]);
                ldsm4(stb + 8192 + pA1[ma] + swz, aL[ma]);
            }
            uint32_t bH[2][4], bL[2][4];
#pragma unroll
            for (int nb = 0; nb < 2; nb++) {
                uint32_t swz = (uint32_t)(((pB2[nb] + ks * 2 + segAdd) ^ pB3[nb]) << 4);
                ldsm4(stb + 16384 + pB1[nb] + swz, bH[nb]);
                ldsm4(stb + 16384 + 8192 + pB1[nb] + swz, bL[nb]);
            }
#pragma unroll
            for (int ma = 0; ma < 4; ma++)
#pragma unroll
                for (int na = 0; na < 4; na++) {
                    uint32_t b0h = bH[na >> 1][na & 1], b1h = bH[na >> 1][2 + (na & 1)];
                    uint32_t b0l = bL[na >> 1][na & 1], b1l = bL[na >> 1][2 + (na & 1)];
                    mma16816(acc[ma][na], aH[ma], b0h, b1h);
                    mma16816(acc[ma][na], aH[ma], b0l, b1l);
                    mma16816(acc[ma][na], aL[ma], b0h, b1h);
                }
        }
        st = (st + 1 == N_STAGES) ? 0 : st + 1;
        ld = (ld + 1 == N_STAGES) ? 0 : ld + 1;
    }

    // ---- epilogue
    const int tr = lane >> 2, tc = (lane & 3) * 2;
#pragma unroll
    for (int ma = 0; ma < 4; ma++) {
        const int r0 = m0 + wm * 64 + ma * 16 + tr;
#pragma unroll
        for (int na = 0; na < 4; na++) {
            const int col = n0 + wn * 32 + na * 8 + tc;
            if (MODE == 2 && col >= 64) continue;
            const float b0 = bias[col], b1 = bias[col + 1];
            float v00 = acc[ma][na][0] + b0, v01 = acc[ma][na][1] + b1;
            float v10 = acc[ma][na][2] + b0, v11 = acc[ma][na][3] + b1;
            if (MODE != 2) {
                v00 = fmaxf(v00, 0.f); v01 = fmaxf(v01, 0.f);
                v10 = fmaxf(v10, 0.f); v11 = fmaxf(v11, 0.f);
            }
            if (MODE == 1 || MODE == 2) {
                *(float2*)(outF + (size_t)r0 * ldC + col) = make_float2(v00, v01);
                *(float2*)(outF + (size_t)(r0 + 8) * ldC + col) = make_float2(v10, v11);
            }
            if (MODE == 0 || MODE == 1) {
                __nv_bfloat162 h0, h1, l0, l1;
                h0.x = __float2bfloat16_rn(v00); h0.y = __float2bfloat16_rn(v01);
                h1.x = __float2bfloat16_rn(v10); h1.y = __float2bfloat16_rn(v11);
                l0.x = __float2bfloat16_rn(v00 - __bfloat162float(h0.x));
                l0.y = __float2bfloat16_rn(v01 - __bfloat162float(h0.y));
                l1.x = __float2bfloat16_rn(v10 - __bfloat162float(h1.x));
                l1.y = __float2bfloat16_rn(v11 - __bfloat162float(h1.y));
                *(__nv_bfloat162*)(outH + (size_t)r0 * ldC + col) = h0;
                *(__nv_bfloat162*)(outH + (size_t)(r0 + 8) * ldC + col) = h1;
                *(__nv_bfloat162*)(outL + (size_t)r0 * ldC + col) = l0;
                *(__nv_bfloat162*)(outL + (size_t)(r0 + 8) * ldC + col) = l1;
            }
        }
    }
}

// ---------------------------------------------------------------------------
// heads postprocess: per-row class softmax + split cls/det (ghd ld = 64)
// ---------------------------------------------------------------------------
__global__ __launch_bounds__(256) void headpost_kernel(
    const float* __restrict__ ghd, float* __restrict__ clsO,
    float* __restrict__ detO, float* __restrict__ cprob) {
    const int row = blockIdx.x * 8 + (threadIdx.x >> 5);
    const int lane = threadIdx.x & 31;
    const bool act = lane < K_;
    float c = act ? ghd[(size_t)row * 64 + lane] : -INFINITY;
    float d = act ? ghd[(size_t)row * 64 + K_ + lane] : 0.f;
    float mx = warp_max(c);
    float e = act ? expf(c - mx) : 0.f;
    float s = warp_sum(e);
    if (act) {
        clsO[(size_t)row * K_ + lane] = c;
        detO[(size_t)row * K_ + lane] = d;
        cprob[(size_t)row * K_ + lane] = e / s;
    }
}

// ---------------------------------------------------------------------------
// fused det-softmax + joint + video: one block per (b,k)
// ---------------------------------------------------------------------------
__global__ __launch_bounds__(256) void detjoint_kernel(
    const float* __restrict__ detL, const float* __restrict__ cprob,
    float* __restrict__ joint, float* __restrict__ video) {
    const int bk = blockIdx.x;
    const int b = bk / K_, k = bk % K_;
    const int tid = threadIdx.x;
    const int warp = tid >> 5, lane = tid & 31;
    __shared__ float red[8];

    const size_t i0 = ((size_t)(b * P_ + tid)) * K_ + k;
    const size_t i1 = ((size_t)(b * P_ + tid + 256)) * K_ + k;
    const float v0 = detL[i0], v1 = detL[i1];

    // block max
    float mx = warp_max(fmaxf(v0, v1));
    if (lane == 0) red[warp] = mx;
    __syncthreads();
    float bm = red[0];
#pragma unroll
    for (int i = 1; i < 8; i++) bm = fmaxf(bm, red[i]);

    // block sumexp
    const float e0 = expf(v0 - bm), e1 = expf(v1 - bm);
    float sm = warp_sum(e0 + e1);
    __syncthreads();
    if (lane == 0) red[warp] = sm;
    __syncthreads();
    float bs = 0.f;
#pragma unroll
    for (int i = 0; i < 8; i++) bs += red[i];
    const float inv = 1.f / bs;

    // joint + video sum
    const float j0 = cprob[i0] * e0 * inv;
    const float j1 = cprob[i1] * e1 * inv;
    joint[i0] = j0;
    joint[i1] = j1;
    float js = warp_sum(j0 + j1);
    __syncthreads();
    if (lane == 0) red[warp] = js;
    __syncthreads();
    if (tid == 0) {
        float tot = 0.f;
#pragma unroll
        for (int i = 0; i < 8; i++) tot += red[i];
        video[bk] = tot;
    }
}

// ---------------------------------------------------------------------------
extern "C" void kernel_launch(void* const* d_in, const int* in_sizes, int n_in,
                              void* d_out, int out_size) {
    const float* x  = (const float*)d_in[0];
    const void*  bx = d_in[1];
    const float* W6 = (const float*)d_in[2];
    const float* b6 = (const float*)d_in[3];
    const float* W7 = (const float*)d_in[4];
    const float* b7 = (const float*)d_in[5];
    const float* Wc = (const float*)d_in[6];
    const float* bc = (const float*)d_in[7];
    const float* Wd = (const float*)d_in[8];
    const float* bd = (const float*)d_in[9];
    float* out = (float*)d_out;

    float *pooled, *bhd, *ghd, *cprob;
    __nv_bfloat16 *fH, *fL, *W6H, *W6L, *W7H, *W7L, *h6H, *h6L, *h7H, *h7L, *WhdH, *WhdL;
    cudaGetSymbolAddress((void**)&pooled, g_pooled);
    cudaGetSymbolAddress((void**)&fH, g_fH);   cudaGetSymbolAddress((void**)&fL, g_fL);
    cudaGetSymbolAddress((void**)&W6H, g_W6H); cudaGetSymbolAddress((void**)&W6L, g_W6L);
    cudaGetSymbolAddress((void**)&W7H, g_W7H); cudaGetSymbolAddress((void**)&W7L, g_W7L);
    cudaGetSymbolAddress((void**)&h6H, g_h6H); cudaGetSymbolAddress((void**)&h6L, g_h6L);
    cudaGetSymbolAddress((void**)&h7H, g_h7H); cudaGetSymbolAddress((void**)&h7L, g_h7L);
    cudaGetSymbolAddress((void**)&WhdH, g_WhdH); cudaGetSymbolAddress((void**)&WhdL, g_WhdL);
    cudaGetSymbolAddress((void**)&bhd, g_bhd);
    cudaGetSymbolAddress((void**)&ghd, g_ghd);
    cudaGetSymbolAddress((void**)&cprob, g_cprob);

    float* h7    = out + H7_OFF;
    float* clsO  = out + CLS_OFF;
    float* detO  = out + DET_OFF;
    float* joint = out + JOINT_OFF;
    float* video = out + VIDEO_OFF;

    const int SMEM = N_STAGES * STG_BYTES;   // 96 KB
    cudaFuncSetAttribute(gemm_mma<0>, cudaFuncAttributeMaxDynamicSharedMemorySize, SMEM);
    cudaFuncSetAttribute(gemm_mma<1>, cudaFuncAttributeMaxDynamicSharedMemorySize, SMEM);
    cudaFuncSetAttribute(gemm_mma<2>, cudaFuncAttributeMaxDynamicSharedMemorySize, SMEM);

    // 1. pooled [B*C, P]
    pool_kernel<<<B_ * C_, 256>>>(x, bx, pooled);
    // 2. feats bf16 hi/lo [M, C]
    transpose_split<<<dim3(C_ / 32, P_ / 32, B_), dim3(32, 8)>>>(pooled, fH, fL);
    // 3. all weight prep in one launch
    prep_all<<<592, 256>>>(W6, W7, Wc, bc, Wd, bd, W6H, W6L, W7H, W7L, WhdH, WhdL, bhd);

    // 4. h6 = relu(feats @ W6^T + b6) : M=4096, N=1024, K=512
    gemm_mma<0><<<dim3(8, 32), 256, SMEM>>>(fH, fL, W6H, W6L, b6, 512, 1024,
                                            nullptr, h6H, h6L);
    // 5. h7 = relu(h6 @ W7^T + b7) : M=4096, N=512, K=1024 (f32 -> out + bf16 pair)
    gemm_mma<1><<<dim3(4, 32), 256, SMEM>>>(h6H, h6L, W7H, W7L, b7, 1024, 512,
                                            h7, h7H, h7L);
    // 6. heads: ghd = h7 @ Whd^T + bhd : M=4096, N=128(pad, store 64), K=512
    gemm_mma<2><<<dim3(1, 32), 256, SMEM>>>(h7H, h7L, WhdH, WhdL, bhd, 512, 64,
                                            ghd, nullptr, nullptr);

    // 7. class softmax + split
    headpost_kernel<<<M_ / 8, 256>>>(ghd, clsO, detO, cprob);
    // 8. fused det softmax + joint + video
    detjoint_kernel<<<B_ * K_, 256>>>(detO, cprob, joint, video);
}